// round 13
// baseline (speedup 1.0000x reference)
#include <cuda_runtime.h>
#include <cuda_bf16.h>
#include <math.h>
#include <stdint.h>

// Problem constants: B=8, 64x64 image -> N=4096, C=512, head_dim=32 -> 16 heads
#define PB   8
#define PH   64
#define PW   64
#define PN   4096
#define PC   512
#define PHD  32
#define PNH  16
#define PM   (PB*PN)       // 32768 GEMM rows
#define PK   512           // GEMM K
#define PNO  1024          // GEMM out cols (2C)

// -------- scratch (device globals; no runtime allocations allowed) --------
__device__ float g_qk[(size_t)PM * PNO];            // 128 MiB qk, processed in place
__device__ float g_ksum[PB * PC];
__device__ float g_kv[PB * PNH * PHD * PHD];        // 131072 elements
__device__ __nv_bfloat16 g_xh[(size_t)PM * PK];
__device__ __nv_bfloat16 g_xl[(size_t)PM * PK];
__device__ __nv_bfloat16 g_wh[(size_t)PNO * PK];
__device__ __nv_bfloat16 g_wl[(size_t)PNO * PK];
__device__ float2 g_rope[64 * 256];                 // cos/sin table: pos x pair
__device__ float g_rs[PC];                          // 1/softplus(scale_p)

// ================= helpers (baseline PTX only) =================
__device__ __forceinline__ uint32_t smem_u32(const void* p) {
    uint32_t a;
    asm("{ .reg .u64 t; cvta.to.shared.u64 t, %1; cvt.u32.u64 %0, t; }" : "=r"(a) : "l"(p));
    return a;
}
__device__ __forceinline__ void cp16(uint32_t sdst, const void* gsrc) {
    asm volatile("cp.async.cg.shared.global [%0], [%1], 16;"
                 :: "r"(sdst), "l"((unsigned long long)__cvta_generic_to_global(gsrc)) : "memory");
}
__device__ __forceinline__ void cp_commit() { asm volatile("cp.async.commit_group;" ::: "memory"); }
__device__ __forceinline__ void cp_wait1()  { asm volatile("cp.async.wait_group 1;" ::: "memory"); }

__device__ __forceinline__ void ldsm4(uint32_t r[4], uint32_t a) {
    asm volatile("ldmatrix.sync.aligned.m8n8.x4.shared.b16 {%0,%1,%2,%3}, [%4];"
                 : "=r"(r[0]), "=r"(r[1]), "=r"(r[2]), "=r"(r[3]) : "r"(a));
}
__device__ __forceinline__ void mma16816(float c[4], const uint32_t a[4], const uint32_t b[2]) {
    asm volatile("mma.sync.aligned.m16n8k16.row.col.f32.bf16.bf16.f32 "
                 "{%0,%1,%2,%3}, {%4,%5,%6,%7}, {%8,%9}, {%0,%1,%2,%3};"
                 : "+f"(c[0]), "+f"(c[1]), "+f"(c[2]), "+f"(c[3])
                 : "r"(a[0]), "r"(a[1]), "r"(a[2]), "r"(a[3]), "r"(b[0]), "r"(b[1]));
}
__device__ __forceinline__ uint32_t swz(uint32_t base, int row, int seg) {
    return base + (uint32_t)row * 64u + (uint32_t)(((seg ^ ((row >> 1) & 3)) & 3) << 4);
}

// ================= K0: f32 -> bf16 hi/lo split =================
__global__ __launch_bounds__(256) void k_cvt(const float* __restrict__ src, int which, int n4) {
    int i = blockIdx.x * 256 + threadIdx.x;
    if (i >= n4) return;
    __nv_bfloat16* hi = which ? g_wh : g_xh;
    __nv_bfloat16* lo = which ? g_wl : g_xl;
    float4 v = ((const float4*)src)[i];
    __nv_bfloat16 h0 = __float2bfloat16_rn(v.x), h1 = __float2bfloat16_rn(v.y);
    __nv_bfloat16 h2 = __float2bfloat16_rn(v.z), h3 = __float2bfloat16_rn(v.w);
    __nv_bfloat16 l0 = __float2bfloat16_rn(v.x - __bfloat162float(h0));
    __nv_bfloat16 l1 = __float2bfloat16_rn(v.y - __bfloat162float(h1));
    __nv_bfloat16 l2 = __float2bfloat16_rn(v.z - __bfloat162float(h2));
    __nv_bfloat16 l3 = __float2bfloat16_rn(v.w - __bfloat162float(h3));
    __nv_bfloat162 hp0 = __halves2bfloat162(h0, h1), hp1 = __halves2bfloat162(h2, h3);
    __nv_bfloat162 lp0 = __halves2bfloat162(l0, l1), lp1 = __halves2bfloat162(l2, l3);
    uint2 hu, lu;
    hu.x = *(uint32_t*)&hp0; hu.y = *(uint32_t*)&hp1;
    lu.x = *(uint32_t*)&lp0; lu.y = *(uint32_t*)&lp1;
    ((uint2*)hi)[i] = hu;
    ((uint2*)lo)[i] = lu;
}

// ====== K0b: RoPE sincos + softplus-recip tables; zero ALL accumulators ======
// 512 blocks x 256 = 131072 threads: covers g_kv (131072) fully every call.
__global__ __launch_bounds__(256) void k_tab(const float* __restrict__ scale_p) {
    int i = blockIdx.x * 256 + threadIdx.x;
    if (i < 16384) {
        int pos = i >> 8, p = i & 255;
        const float LOG1E4 = 9.2103403719761836f;
        float theta = expf(-(float)(p & 127) * (LOG1E4 / 128.f));
        float sn, cs;
        sincosf((float)pos * theta, &sn, &cs);
        g_rope[i] = make_float2(cs, sn);
        if (i < PC) g_rs[i] = 1.f / logf(1.f + expf(scale_p[i]));
        if (i < PB * PC) g_ksum[i] = 0.f;
    }
    if (i < PB * PNH * PHD * PHD) g_kv[i] = 0.f;
}

// ================= K6: depthwise 5x5 conv — 4-wide width x 4-way height split ==========
// block = (wgroup of 4 widths, height-slice of 16, batch); 512 threads = channels
__global__ __launch_bounds__(512) void k_conv(const float* __restrict__ x,
                                              const float* __restrict__ wt,
                                              const float* __restrict__ bias,
                                              float* __restrict__ out) {
    const int b = blockIdx.z;
    const int hbeg = blockIdx.y * 16;            // output rows hbeg..hbeg+15
    const int wbase = blockIdx.x * 4;            // output cols wbase..wbase+3
    const int c = threadIdx.x;
    const int d = c & (PHD - 1);

    float wv[25];
#pragma unroll
    for (int t = 0; t < 25; t++) wv[t] = wt[d * 25 + t];
    const float bv = bias[d];

    float r[5][8];

    auto ld = [&](float dst[8], int rowidx) {
        if (rowidx < 0 || rowidx >= PH) {
#pragma unroll
            for (int dw = 0; dw < 8; dw++) dst[dw] = 0.f;
            return;
        }
#pragma unroll
        for (int dw = 0; dw < 8; dw++) {
            int w2 = wbase - 2 + dw;
            dst[dw] = (w2 >= 0 && w2 < PW)
                ? x[((size_t)b * PN + rowidx * PW + w2) * PC + c] : 0.f;
        }
    };
    ld(r[0], hbeg - 2); ld(r[1], hbeg - 1); ld(r[2], hbeg);
    ld(r[3], hbeg + 1); ld(r[4], hbeg + 2);

    for (int ho = hbeg; ho < hbeg + 16; ho++) {
#pragma unroll
        for (int ow = 0; ow < 4; ow++) {
            float s = bv;
#pragma unroll
            for (int kh = 0; kh < 5; kh++)
#pragma unroll
                for (int kw = 0; kw < 5; kw++)
                    s = fmaf(r[kh][ow + kw], wv[kh * 5 + kw], s);
            out[((size_t)b * PN + ho * PW + wbase + ow) * PC + c] = s;
        }
#pragma unroll
        for (int j = 0; j < 4; j++)
#pragma unroll
            for (int dw = 0; dw < 8; dw++) r[j][dw] = r[j + 1][dw];
        ld(r[4], ho + 3);
    }
}

// ================= K1: bf16-split GEMM via mma.sync (known-good) ==========
#define NSTAGE 3
#define STG_BYTES 32768
#define GSM_TOT (NSTAGE * STG_BYTES)
#define NCHUNK 16

__device__ __forceinline__ void load_stage(uint32_t sbase, int kc, int bm, int bn, int tid) {
#pragma unroll
    for (int j = 0; j < 2; j++) {
        int idx = j * 256 + tid;
        int row = idx >> 2, seg = idx & 3;
        size_t go = (size_t)kc * 32 + seg * 8;
        cp16(swz(sbase +     0, row, seg), g_xh + ((size_t)(bm + row) << 9) + go);
        cp16(swz(sbase +  8192, row, seg), g_xl + ((size_t)(bm + row) << 9) + go);
        cp16(swz(sbase + 16384, row, seg), g_wh + ((size_t)(bn + row) << 9) + go);
        cp16(swz(sbase + 24576, row, seg), g_wl + ((size_t)(bn + row) << 9) + go);
    }
}

__global__ __launch_bounds__(256) void k_gemm_mma(const float* __restrict__ bias) {
    extern __shared__ __align__(128) char smraw[];
    uint32_t sb = smem_u32(smraw);
    const int tid = threadIdx.x;
    const int wid = tid >> 5, lane = tid & 31;
    const int gid = lane >> 2, tig = lane & 3;
    const int q = lane >> 3, lr = lane & 7;
    const int bn = blockIdx.x * 128;
    const int bm = blockIdx.y * 128;
    const int wm = (wid & 1) * 64;
    const int wn = (wid >> 1) * 32;

    float acc[4][4][4];
#pragma unroll
    for (int a = 0; a < 4; a++)
#pragma unroll
        for (int b = 0; b < 4; b++)
#pragma unroll
            for (int cpos = 0; cpos < 4; cpos++) acc[a][b][cpos] = 0.f;

    load_stage(sb + 0 * STG_BYTES, 0, bm, bn, tid); cp_commit();
    load_stage(sb + 1 * STG_BYTES, 1, bm, bn, tid); cp_commit();

    for (int kc = 0; kc < NCHUNK; kc++) {
        cp_wait1();
        __syncthreads();
        if (kc + 2 < NCHUNK)
            load_stage(sb + (uint32_t)((kc + 2) % NSTAGE) * STG_BYTES, kc + 2, bm, bn, tid);
        cp_commit();

        uint32_t st = sb + (uint32_t)(kc % NSTAGE) * STG_BYTES;
        uint32_t Ah = st, Al = st + 8192, Bh = st + 16384, Bl = st + 24576;
#pragma unroll
        for (int ks = 0; ks < 2; ks++) {
            uint32_t ah[4][4], al[4][4], bh[4][2], bl[4][2];
            int arow = wm + lr + (q & 1) * 8;
            int aseg = 2 * ks + (q >> 1);
#pragma unroll
            for (int mt = 0; mt < 4; mt++) {
                ldsm4(ah[mt], swz(Ah, arow + mt * 16, aseg));
                ldsm4(al[mt], swz(Al, arow + mt * 16, aseg));
            }
            int brow = wn + lr + (q >> 1) * 8;
            int bseg = 2 * ks + (q & 1);
#pragma unroll
            for (int p = 0; p < 2; p++) {
                uint32_t t4[4];
                ldsm4(t4, swz(Bh, brow + p * 16, bseg));
                bh[2 * p][0] = t4[0]; bh[2 * p][1] = t4[1];
                bh[2 * p + 1][0] = t4[2]; bh[2 * p + 1][1] = t4[3];
                ldsm4(t4, swz(Bl, brow + p * 16, bseg));
                bl[2 * p][0] = t4[0]; bl[2 * p][1] = t4[1];
                bl[2 * p + 1][0] = t4[2]; bl[2 * p + 1][1] = t4[3];
            }
#pragma unroll
            for (int mt = 0; mt < 4; mt++)
#pragma unroll
                for (int nt = 0; nt < 4; nt++) {
                    mma16816(acc[mt][nt], ah[mt], bh[nt]);
                    mma16816(acc[mt][nt], ah[mt], bl[nt]);
                    mma16816(acc[mt][nt], al[mt], bh[nt]);
                }
        }
    }

#pragma unroll
    for (int mt = 0; mt < 4; mt++) {
        int r0 = bm + wm + mt * 16 + gid;
#pragma unroll
        for (int nt = 0; nt < 4; nt++) {
            int cb = bn + wn + nt * 8 + 2 * tig;
            float b0 = bias[cb], b1 = bias[cb + 1];
            float2 v0 = make_float2(acc[mt][nt][0] + b0, acc[mt][nt][1] + b1);
            float2 v1 = make_float2(acc[mt][nt][2] + b0, acc[mt][nt][3] + b1);
            *(float2*)&g_qk[(size_t)r0 * PNO + cb] = v0;
            *(float2*)&g_qk[(size_t)(r0 + 8) * PNO + cb] = v1;
        }
    }
}

// ================= K2: per-token transform — table-driven =================
__global__ __launch_bounds__(256) void k_post() {
    const int token = blockIdx.x;
    const int n = token & (PN - 1);
    const int hi = n >> 6;
    const int wi = n & 63;
    const int p = threadIdx.x;
    float* row = g_qk + (size_t)token * PNO;

    const int pos = (p < 128) ? hi : wi;
    float2 cssn = g_rope[pos * 256 + p];
    float cs = cssn.x, sn = cssn.y;

    float2 qv = *(float2*)&row[2 * p];
    float2 kvv = *(float2*)&row[PC + 2 * p];
    float2 rs = *(float2*)&g_rs[2 * p];

    float q0 = qv.x * cs - qv.y * sn, q1 = qv.y * cs + qv.x * sn;
    float k0 = kvv.x * cs - kvv.y * sn, k1 = kvv.y * cs + kvv.x * sn;

    q0 = q0 > 0.f ? q0 + 1.f : __expf(q0);
    q1 = q1 > 0.f ? q1 + 1.f : __expf(q1);
    k0 = k0 > 0.f ? k0 + 1.f : __expf(k0);
    k1 = k1 > 0.f ? k1 + 1.f : __expf(k1);

    q0 *= rs.x; q1 *= rs.y; k0 *= rs.x; k1 *= rs.y;

    float q0c = q0 * q0 * q0, q1c = q1 * q1 * q1;
    float k0c = k0 * k0 * k0, k1c = k1 * k1 * k1;
    float v0 = q0 * q0 + q1 * q1;
    float v1 = q0c * q0c + q1c * q1c;
    float v2 = k0 * k0 + k1 * k1;
    float v3 = k0c * k0c + k1c * k1c;

    __shared__ float warpsum[8][4];
    float v[4] = {v0, v1, v2, v3};
    const int lane = p & 31, wd = p >> 5;
#pragma unroll
    for (int t = 0; t < 4; t++) {
        float s = v[t];
#pragma unroll
        for (int off = 16; off > 0; off >>= 1) s += __shfl_down_sync(0xffffffffu, s, off);
        if (lane == 0) warpsum[wd][t] = s;
    }
    __syncthreads();
    __shared__ float fac[2];
    if (p == 0) {
        float s[4] = {0.f, 0.f, 0.f, 0.f};
        for (int w = 0; w < 8; w++)
            for (int t = 0; t < 4; t++) s[t] += warpsum[w][t];
        fac[0] = sqrtf(s[0] / s[1]);
        fac[1] = sqrtf(s[2] / s[3]);
    }
    __syncthreads();
    float fq = fac[0], fk = fac[1];
    *(float2*)&row[2 * p]      = make_float2(q0c * fq, q1c * fq);
    *(float2*)&row[PC + 2 * p] = make_float2(k0c * fk, k1c * fk);
}

// ================= K3: k-sums =================
__global__ __launch_bounds__(512) void k_ksum() {
    const int b = blockIdx.x >> 5;
    const int chunk = blockIdx.x & 31;
    const int c = threadIdx.x;
    float s = 0.f;
    const size_t base = ((size_t)b * PN + chunk * 128) * PNO + PC + c;
    for (int r = 0; r < 128; r++) s += g_qk[base + (size_t)r * PNO];
    atomicAdd(&g_ksum[b * PC + c], s);
}

// ================= K4: kv = k^T v — 16-way n-split, atomic reduce =================
__global__ __launch_bounds__(256) void k_kv(const float* __restrict__ x) {
    const int b = blockIdx.x >> 8;           // 8 * 16 * 16 = 2048 blocks
    const int h = (blockIdx.x >> 4) & 15;
    const int sl = blockIdx.x & 15;          // n slice: 256 rows
    const int tid = threadIdx.x;
    const int e = tid & 31;
    const int dg = tid >> 5;

    __shared__ __align__(16) float sk[32][36];
    __shared__ __align__(16) float sv[32][36];

    float acc[4] = {0.f, 0.f, 0.f, 0.f};
    const int lr = tid >> 5, lc = tid & 31;
    const int n0beg = sl * 256, n0end = n0beg + 256;

    for (int n0 = n0beg; n0 < n0end; n0 += 32) {
        __syncthreads();
#pragma unroll
        for (int rr = lr; rr < 32; rr += 8) {
            size_t rbase = ((size_t)b * PN + n0 + rr);
            sk[rr][lc] = g_qk[rbase * PNO + PC + h * PHD + lc];
            sv[rr][lc] = x[rbase * PC + h * PHD + lc];
        }
        __syncthreads();
#pragma unroll 8
        for (int nn = 0; nn < 32; nn++) {
            float vv = sv[nn][e];
            float4 kk = *(const float4*)&sk[nn][dg * 4];
            acc[0] = fmaf(kk.x, vv, acc[0]);
            acc[1] = fmaf(kk.y, vv, acc[1]);
            acc[2] = fmaf(kk.z, vv, acc[2]);
            acc[3] = fmaf(kk.w, vv, acc[3]);
        }
    }
    const float s2 = 1.f / (float)PN;
#pragma unroll
    for (int i = 0; i < 4; i++)
        atomicAdd(&g_kv[(((size_t)b * PNH + h) * PHD + dg * 4 + i) * PHD + e], acc[i] * s2);
}

// ================= K5: out += (q@kv)*z =================
__global__ __launch_bounds__(256) void k_att(float* __restrict__ out) {
    const int bid = blockIdx.x;
    const int b = bid >> 9;
    const int h = (bid >> 5) & 15;
    const int tile = bid & 31;
    const int tid = threadIdx.x;
    const int lane = tid & 31;
    const int w = tid >> 5;

    __shared__ float skv[32][33];
    __shared__ float skm[32];
    __shared__ float sq[8][32];

    for (int i = tid; i < 1024; i += 256)
        skv[i >> 5][i & 31] = g_kv[((size_t)b * PNH + h) * 1024 + i];
    if (tid < 32)
        skm[tid] = g_ksum[b * PC + h * PHD + tid] * (1.f / (float)PN);
    __syncthreads();

    for (int chunk = 0; chunk < 16; chunk++) {
        int t = tile * 128 + chunk * 8 + w;
        float qv = g_qk[((size_t)b * PN + t) * PNO + h * PHD + lane];
        __syncwarp();
        sq[w][lane] = qv;
        __syncwarp();
        float zdot = 0.f, acc = 0.f;
#pragma unroll
        for (int d = 0; d < 32; d++) {
            float qd = sq[w][d];
            zdot = fmaf(qd, skm[d], zdot);
            acc  = fmaf(qd, skv[d][lane], acc);
        }
        float z = 1.f / (zdot + 1e-6f);
        out[((size_t)b * PN + t) * PC + h * PHD + lane] += acc * z;
    }
}

// ================= launch =================
extern "C" void kernel_launch(void* const* d_in, const int* in_sizes, int n_in,
                              void* d_out, int out_size) {
    (void)in_sizes; (void)n_in; (void)out_size;
    const float* x       = (const float*)d_in[0];
    const float* W_qk    = (const float*)d_in[1];
    const float* b_qk    = (const float*)d_in[2];
    const float* scale_p = (const float*)d_in[3];
    const float* dwc_w   = (const float*)d_in[4];
    const float* dwc_b   = (const float*)d_in[5];
    float* out = (float*)d_out;

    cudaFuncSetAttribute(k_gemm_mma, cudaFuncAttributeMaxDynamicSharedMemorySize, GSM_TOT);

    // k_conv stays 4th so the profiler's fixed capture index verifies the split
    k_cvt<<<(PM * PK / 4 + 255) / 256, 256>>>(x, 0, PM * PK / 4);
    k_cvt<<<(PNO * PK / 4 + 255) / 256, 256>>>(W_qk, 1, PNO * PK / 4);
    k_tab<<<512, 256>>>(scale_p);                              // tables + FULL zeroing
    k_conv<<<dim3(PW / 4, 4, PB), 512>>>(x, dwc_w, dwc_b, out);// writes out (+bias)
    k_gemm_mma<<<dim3(PNO / 128, PM / 128), 256, GSM_TOT>>>(b_qk);
    k_post<<<PM, 256>>>();
    k_ksum<<<PB * 32, 512>>>();
    k_kv<<<PB * PNH * 16, 256>>>(x);
    k_att<<<PB * PNH * 32, 256>>>(out);                        // accumulates
}

// round 16
// speedup vs baseline: 1.0280x; 1.0280x over previous
#include <cuda_runtime.h>
#include <cuda_bf16.h>
#include <math.h>
#include <stdint.h>

// Problem constants: B=8, 64x64 image -> N=4096, C=512, head_dim=32 -> 16 heads
#define PB   8
#define PH   64
#define PW   64
#define PN   4096
#define PC   512
#define PHD  32
#define PNH  16
#define PM   (PB*PN)       // 32768 GEMM rows
#define PK   512           // GEMM K
#define PNO  1024          // GEMM out cols (2C)

// -------- scratch (device globals; no runtime allocations allowed) --------
__device__ float g_qk[(size_t)PM * PNO];            // 128 MiB qk, processed in place
__device__ float g_ksum[PB * PC];
__device__ float g_kv[PB * PNH * PHD * PHD];        // 131072 elements
__device__ __nv_bfloat16 g_xh[(size_t)PM * PK];
__device__ __nv_bfloat16 g_xl[(size_t)PM * PK];
__device__ __nv_bfloat16 g_wh[(size_t)PNO * PK];
__device__ __nv_bfloat16 g_wl[(size_t)PNO * PK];
__device__ float2 g_rope[64 * 256];                 // cos/sin table: pos x pair
__device__ float g_rs[PC];                          // 1/softplus(scale_p)

// ================= helpers (baseline PTX only) =================
__device__ __forceinline__ uint32_t smem_u32(const void* p) {
    uint32_t a;
    asm("{ .reg .u64 t; cvta.to.shared.u64 t, %1; cvt.u32.u64 %0, t; }" : "=r"(a) : "l"(p));
    return a;
}
__device__ __forceinline__ void cp16(uint32_t sdst, const void* gsrc) {
    asm volatile("cp.async.cg.shared.global [%0], [%1], 16;"
                 :: "r"(sdst), "l"((unsigned long long)__cvta_generic_to_global(gsrc)) : "memory");
}
__device__ __forceinline__ void cp_commit() { asm volatile("cp.async.commit_group;" ::: "memory"); }
__device__ __forceinline__ void cp_wait1()  { asm volatile("cp.async.wait_group 1;" ::: "memory"); }

__device__ __forceinline__ void ldsm4(uint32_t r[4], uint32_t a) {
    asm volatile("ldmatrix.sync.aligned.m8n8.x4.shared.b16 {%0,%1,%2,%3}, [%4];"
                 : "=r"(r[0]), "=r"(r[1]), "=r"(r[2]), "=r"(r[3]) : "r"(a));
}
__device__ __forceinline__ void mma16816(float c[4], const uint32_t a[4], const uint32_t b[2]) {
    asm volatile("mma.sync.aligned.m16n8k16.row.col.f32.bf16.bf16.f32 "
                 "{%0,%1,%2,%3}, {%4,%5,%6,%7}, {%8,%9}, {%0,%1,%2,%3};"
                 : "+f"(c[0]), "+f"(c[1]), "+f"(c[2]), "+f"(c[3])
                 : "r"(a[0]), "r"(a[1]), "r"(a[2]), "r"(a[3]), "r"(b[0]), "r"(b[1]));
}
__device__ __forceinline__ uint32_t swz(uint32_t base, int row, int seg) {
    return base + (uint32_t)row * 64u + (uint32_t)(((seg ^ ((row >> 1) & 3)) & 3) << 4);
}

// ================= K0: f32 -> bf16 hi/lo split =================
__global__ __launch_bounds__(256) void k_cvt(const float* __restrict__ src, int which, int n4) {
    int i = blockIdx.x * 256 + threadIdx.x;
    if (i >= n4) return;
    __nv_bfloat16* hi = which ? g_wh : g_xh;
    __nv_bfloat16* lo = which ? g_wl : g_xl;
    float4 v = ((const float4*)src)[i];
    __nv_bfloat16 h0 = __float2bfloat16_rn(v.x), h1 = __float2bfloat16_rn(v.y);
    __nv_bfloat16 h2 = __float2bfloat16_rn(v.z), h3 = __float2bfloat16_rn(v.w);
    __nv_bfloat16 l0 = __float2bfloat16_rn(v.x - __bfloat162float(h0));
    __nv_bfloat16 l1 = __float2bfloat16_rn(v.y - __bfloat162float(h1));
    __nv_bfloat16 l2 = __float2bfloat16_rn(v.z - __bfloat162float(h2));
    __nv_bfloat16 l3 = __float2bfloat16_rn(v.w - __bfloat162float(h3));
    __nv_bfloat162 hp0 = __halves2bfloat162(h0, h1), hp1 = __halves2bfloat162(h2, h3);
    __nv_bfloat162 lp0 = __halves2bfloat162(l0, l1), lp1 = __halves2bfloat162(l2, l3);
    uint2 hu, lu;
    hu.x = *(uint32_t*)&hp0; hu.y = *(uint32_t*)&hp1;
    lu.x = *(uint32_t*)&lp0; lu.y = *(uint32_t*)&lp1;
    ((uint2*)hi)[i] = hu;
    ((uint2*)lo)[i] = lu;
}

// ====== K0b: RoPE sincos + softplus-recip tables; zero ALL accumulators ======
// 512 blocks x 256 = 131072 threads: covers g_kv (131072) fully every call.
__global__ __launch_bounds__(256) void k_tab(const float* __restrict__ scale_p) {
    int i = blockIdx.x * 256 + threadIdx.x;
    if (i < 16384) {
        int pos = i >> 8, p = i & 255;
        const float LOG1E4 = 9.2103403719761836f;
        float theta = expf(-(float)(p & 127) * (LOG1E4 / 128.f));
        float sn, cs;
        sincosf((float)pos * theta, &sn, &cs);
        g_rope[i] = make_float2(cs, sn);
        if (i < PC) g_rs[i] = 1.f / logf(1.f + expf(scale_p[i]));
        if (i < PB * PC) g_ksum[i] = 0.f;
    }
    if (i < PB * PNH * PHD * PHD) g_kv[i] = 0.f;
}

// ======== K6: depthwise 5x5 conv — 4-wide, 2-way height split, smem weights ========
// __launch_bounds__(512,2): <=64 regs -> 2 CTAs/SM; grid (16,2,8)=256 = one wave.
__global__ __launch_bounds__(512, 2) void k_conv(const float* __restrict__ x,
                                                 const float* __restrict__ wt,
                                                 const float* __restrict__ bias,
                                                 float* __restrict__ out) {
    __shared__ float swt[25 * PHD + PHD];        // 832 floats: weights + bias
    const int b = blockIdx.z;
    const int hbeg = blockIdx.y * 32;            // output rows hbeg..hbeg+31
    const int wbase = blockIdx.x * 4;            // output cols wbase..wbase+3
    const int c = threadIdx.x;
    const int d = c & (PHD - 1);

    for (int t = c; t < 25 * PHD; t += 512) swt[t] = wt[t];   // 800 weights, 512 threads
    if (c < PHD) swt[25 * PHD + c] = bias[c];
    __syncthreads();
    const float bv = swt[25 * PHD + d];
    const float* wp = &swt[d * 25];

    float r[5][8];
    auto ld = [&](float dst[8], int rowidx) {
        if (rowidx < 0 || rowidx >= PH) {
#pragma unroll
            for (int dw = 0; dw < 8; dw++) dst[dw] = 0.f;
            return;
        }
#pragma unroll
        for (int dw = 0; dw < 8; dw++) {
            int w2 = wbase - 2 + dw;
            dst[dw] = (w2 >= 0 && w2 < PW)
                ? x[((size_t)b * PN + rowidx * PW + w2) * PC + c] : 0.f;
        }
    };
    ld(r[0], hbeg - 2); ld(r[1], hbeg - 1); ld(r[2], hbeg);
    ld(r[3], hbeg + 1); ld(r[4], hbeg + 2);

    for (int ho = hbeg; ho < hbeg + 32; ho++) {
        float s[4] = {bv, bv, bv, bv};
#pragma unroll
        for (int kh = 0; kh < 5; kh++) {
            float w0 = wp[kh * 5 + 0], w1 = wp[kh * 5 + 1], w2 = wp[kh * 5 + 2];
            float w3 = wp[kh * 5 + 3], w4 = wp[kh * 5 + 4];
#pragma unroll
            for (int ow = 0; ow < 4; ow++) {
                s[ow] = fmaf(r[kh][ow + 0], w0, s[ow]);
                s[ow] = fmaf(r[kh][ow + 1], w1, s[ow]);
                s[ow] = fmaf(r[kh][ow + 2], w2, s[ow]);
                s[ow] = fmaf(r[kh][ow + 3], w3, s[ow]);
                s[ow] = fmaf(r[kh][ow + 4], w4, s[ow]);
            }
        }
#pragma unroll
        for (int ow = 0; ow < 4; ow++)
            out[((size_t)b * PN + ho * PW + wbase + ow) * PC + c] = s[ow];
#pragma unroll
        for (int j = 0; j < 4; j++)
#pragma unroll
            for (int dw = 0; dw < 8; dw++) r[j][dw] = r[j + 1][dw];
        ld(r[4], ho + 3);
    }
}

// ================= K1: bf16-split GEMM via mma.sync (known-good) ==========
#define NSTAGE 3
#define STG_BYTES 32768
#define GSM_TOT (NSTAGE * STG_BYTES)
#define NCHUNK 16

__device__ __forceinline__ void load_stage(uint32_t sbase, int kc, int bm, int bn, int tid) {
#pragma unroll
    for (int j = 0; j < 2; j++) {
        int idx = j * 256 + tid;
        int row = idx >> 2, seg = idx & 3;
        size_t go = (size_t)kc * 32 + seg * 8;
        cp16(swz(sbase +     0, row, seg), g_xh + ((size_t)(bm + row) << 9) + go);
        cp16(swz(sbase +  8192, row, seg), g_xl + ((size_t)(bm + row) << 9) + go);
        cp16(swz(sbase + 16384, row, seg), g_wh + ((size_t)(bn + row) << 9) + go);
        cp16(swz(sbase + 24576, row, seg), g_wl + ((size_t)(bn + row) << 9) + go);
    }
}

__global__ __launch_bounds__(256) void k_gemm_mma(const float* __restrict__ bias) {
    extern __shared__ __align__(128) char smraw[];
    uint32_t sb = smem_u32(smraw);
    const int tid = threadIdx.x;
    const int wid = tid >> 5, lane = tid & 31;
    const int gid = lane >> 2, tig = lane & 3;
    const int q = lane >> 3, lr = lane & 7;
    const int bn = blockIdx.x * 128;
    const int bm = blockIdx.y * 128;
    const int wm = (wid & 1) * 64;
    const int wn = (wid >> 1) * 32;

    float acc[4][4][4];
#pragma unroll
    for (int a = 0; a < 4; a++)
#pragma unroll
        for (int b = 0; b < 4; b++)
#pragma unroll
            for (int cpos = 0; cpos < 4; cpos++) acc[a][b][cpos] = 0.f;

    load_stage(sb + 0 * STG_BYTES, 0, bm, bn, tid); cp_commit();
    load_stage(sb + 1 * STG_BYTES, 1, bm, bn, tid); cp_commit();

    for (int kc = 0; kc < NCHUNK; kc++) {
        cp_wait1();
        __syncthreads();
        if (kc + 2 < NCHUNK)
            load_stage(sb + (uint32_t)((kc + 2) % NSTAGE) * STG_BYTES, kc + 2, bm, bn, tid);
        cp_commit();

        uint32_t st = sb + (uint32_t)(kc % NSTAGE) * STG_BYTES;
        uint32_t Ah = st, Al = st + 8192, Bh = st + 16384, Bl = st + 24576;
#pragma unroll
        for (int ks = 0; ks < 2; ks++) {
            uint32_t ah[4][4], al[4][4], bh[4][2], bl[4][2];
            int arow = wm + lr + (q & 1) * 8;
            int aseg = 2 * ks + (q >> 1);
#pragma unroll
            for (int mt = 0; mt < 4; mt++) {
                ldsm4(ah[mt], swz(Ah, arow + mt * 16, aseg));
                ldsm4(al[mt], swz(Al, arow + mt * 16, aseg));
            }
            int brow = wn + lr + (q >> 1) * 8;
            int bseg = 2 * ks + (q & 1);
#pragma unroll
            for (int p = 0; p < 2; p++) {
                uint32_t t4[4];
                ldsm4(t4, swz(Bh, brow + p * 16, bseg));
                bh[2 * p][0] = t4[0]; bh[2 * p][1] = t4[1];
                bh[2 * p + 1][0] = t4[2]; bh[2 * p + 1][1] = t4[3];
                ldsm4(t4, swz(Bl, brow + p * 16, bseg));
                bl[2 * p][0] = t4[0]; bl[2 * p][1] = t4[1];
                bl[2 * p + 1][0] = t4[2]; bl[2 * p + 1][1] = t4[3];
            }
#pragma unroll
            for (int mt = 0; mt < 4; mt++)
#pragma unroll
                for (int nt = 0; nt < 4; nt++) {
                    mma16816(acc[mt][nt], ah[mt], bh[nt]);
                    mma16816(acc[mt][nt], ah[mt], bl[nt]);
                    mma16816(acc[mt][nt], al[mt], bh[nt]);
                }
        }
    }

#pragma unroll
    for (int mt = 0; mt < 4; mt++) {
        int r0 = bm + wm + mt * 16 + gid;
#pragma unroll
        for (int nt = 0; nt < 4; nt++) {
            int cb = bn + wn + nt * 8 + 2 * tig;
            float b0 = bias[cb], b1 = bias[cb + 1];
            float2 v0 = make_float2(acc[mt][nt][0] + b0, acc[mt][nt][1] + b1);
            float2 v1 = make_float2(acc[mt][nt][2] + b0, acc[mt][nt][3] + b1);
            *(float2*)&g_qk[(size_t)r0 * PNO + cb] = v0;
            *(float2*)&g_qk[(size_t)(r0 + 8) * PNO + cb] = v1;
        }
    }
}

// ================= K2: per-token transform — table-driven =================
__global__ __launch_bounds__(256) void k_post() {
    const int token = blockIdx.x;
    const int n = token & (PN - 1);
    const int hi = n >> 6;
    const int wi = n & 63;
    const int p = threadIdx.x;
    float* row = g_qk + (size_t)token * PNO;

    const int pos = (p < 128) ? hi : wi;
    float2 cssn = g_rope[pos * 256 + p];
    float cs = cssn.x, sn = cssn.y;

    float2 qv = *(float2*)&row[2 * p];
    float2 kvv = *(float2*)&row[PC + 2 * p];
    float2 rs = *(float2*)&g_rs[2 * p];

    float q0 = qv.x * cs - qv.y * sn, q1 = qv.y * cs + qv.x * sn;
    float k0 = kvv.x * cs - kvv.y * sn, k1 = kvv.y * cs + kvv.x * sn;

    q0 = q0 > 0.f ? q0 + 1.f : __expf(q0);
    q1 = q1 > 0.f ? q1 + 1.f : __expf(q1);
    k0 = k0 > 0.f ? k0 + 1.f : __expf(k0);
    k1 = k1 > 0.f ? k1 + 1.f : __expf(k1);

    q0 *= rs.x; q1 *= rs.y; k0 *= rs.x; k1 *= rs.y;

    float q0c = q0 * q0 * q0, q1c = q1 * q1 * q1;
    float k0c = k0 * k0 * k0, k1c = k1 * k1 * k1;
    float v0 = q0 * q0 + q1 * q1;
    float v1 = q0c * q0c + q1c * q1c;
    float v2 = k0 * k0 + k1 * k1;
    float v3 = k0c * k0c + k1c * k1c;

    __shared__ float warpsum[8][4];
    float v[4] = {v0, v1, v2, v3};
    const int lane = p & 31, wd = p >> 5;
#pragma unroll
    for (int t = 0; t < 4; t++) {
        float s = v[t];
#pragma unroll
        for (int off = 16; off > 0; off >>= 1) s += __shfl_down_sync(0xffffffffu, s, off);
        if (lane == 0) warpsum[wd][t] = s;
    }
    __syncthreads();
    __shared__ float fac[2];
    if (p == 0) {
        float s[4] = {0.f, 0.f, 0.f, 0.f};
        for (int w = 0; w < 8; w++)
            for (int t = 0; t < 4; t++) s[t] += warpsum[w][t];
        fac[0] = sqrtf(s[0] / s[1]);
        fac[1] = sqrtf(s[2] / s[3]);
    }
    __syncthreads();
    float fq = fac[0], fk = fac[1];
    *(float2*)&row[2 * p]      = make_float2(q0c * fq, q1c * fq);
    *(float2*)&row[PC + 2 * p] = make_float2(k0c * fk, k1c * fk);
}

// ================= K3: k-sums =================
__global__ __launch_bounds__(512) void k_ksum() {
    const int b = blockIdx.x >> 5;
    const int chunk = blockIdx.x & 31;
    const int c = threadIdx.x;
    float s = 0.f;
    const size_t base = ((size_t)b * PN + chunk * 128) * PNO + PC + c;
    for (int r = 0; r < 128; r++) s += g_qk[base + (size_t)r * PNO];
    atomicAdd(&g_ksum[b * PC + c], s);
}

// ================= K4: kv = k^T v — 16-way n-split, atomic reduce =================
__global__ __launch_bounds__(256) void k_kv(const float* __restrict__ x) {
    const int b = blockIdx.x >> 8;           // 8 * 16 * 16 = 2048 blocks
    const int h = (blockIdx.x >> 4) & 15;
    const int sl = blockIdx.x & 15;          // n slice: 256 rows
    const int tid = threadIdx.x;
    const int e = tid & 31;
    const int dg = tid >> 5;

    __shared__ __align__(16) float sk[32][36];
    __shared__ __align__(16) float sv[32][36];

    float acc[4] = {0.f, 0.f, 0.f, 0.f};
    const int lr = tid >> 5, lc = tid & 31;
    const int n0beg = sl * 256, n0end = n0beg + 256;

    for (int n0 = n0beg; n0 < n0end; n0 += 32) {
        __syncthreads();
#pragma unroll
        for (int rr = lr; rr < 32; rr += 8) {
            size_t rbase = ((size_t)b * PN + n0 + rr);
            sk[rr][lc] = g_qk[rbase * PNO + PC + h * PHD + lc];
            sv[rr][lc] = x[rbase * PC + h * PHD + lc];
        }
        __syncthreads();
#pragma unroll 8
        for (int nn = 0; nn < 32; nn++) {
            float vv = sv[nn][e];
            float4 kk = *(const float4*)&sk[nn][dg * 4];
            acc[0] = fmaf(kk.x, vv, acc[0]);
            acc[1] = fmaf(kk.y, vv, acc[1]);
            acc[2] = fmaf(kk.z, vv, acc[2]);
            acc[3] = fmaf(kk.w, vv, acc[3]);
        }
    }
    const float s2 = 1.f / (float)PN;
#pragma unroll
    for (int i = 0; i < 4; i++)
        atomicAdd(&g_kv[(((size_t)b * PNH + h) * PHD + dg * 4 + i) * PHD + e], acc[i] * s2);
}

// ================= K5: out += (q@kv)*z =================
__global__ __launch_bounds__(256) void k_att(float* __restrict__ out) {
    const int bid = blockIdx.x;
    const int b = bid >> 9;
    const int h = (bid >> 5) & 15;
    const int tile = bid & 31;
    const int tid = threadIdx.x;
    const int lane = tid & 31;
    const int w = tid >> 5;

    __shared__ float skv[32][33];
    __shared__ float skm[32];
    __shared__ float sq[8][32];

    for (int i = tid; i < 1024; i += 256)
        skv[i >> 5][i & 31] = g_kv[((size_t)b * PNH + h) * 1024 + i];
    if (tid < 32)
        skm[tid] = g_ksum[b * PC + h * PHD + tid] * (1.f / (float)PN);
    __syncthreads();

    for (int chunk = 0; chunk < 16; chunk++) {
        int t = tile * 128 + chunk * 8 + w;
        float qv = g_qk[((size_t)b * PN + t) * PNO + h * PHD + lane];
        __syncwarp();
        sq[w][lane] = qv;
        __syncwarp();
        float zdot = 0.f, acc = 0.f;
#pragma unroll
        for (int d = 0; d < 32; d++) {
            float qd = sq[w][d];
            zdot = fmaf(qd, skm[d], zdot);
            acc  = fmaf(qd, skv[d][lane], acc);
        }
        float z = 1.f / (zdot + 1e-6f);
        out[((size_t)b * PN + t) * PC + h * PHD + lane] += acc * z;
    }
}

// ================= launch =================
extern "C" void kernel_launch(void* const* d_in, const int* in_sizes, int n_in,
                              void* d_out, int out_size) {
    (void)in_sizes; (void)n_in; (void)out_size;
    const float* x       = (const float*)d_in[0];
    const float* W_qk    = (const float*)d_in[1];
    const float* b_qk    = (const float*)d_in[2];
    const float* scale_p = (const float*)d_in[3];
    const float* dwc_w   = (const float*)d_in[4];
    const float* dwc_b   = (const float*)d_in[5];
    float* out = (float*)d_out;

    cudaFuncSetAttribute(k_gemm_mma, cudaFuncAttributeMaxDynamicSharedMemorySize, GSM_TOT);

    // k_conv stays 4th so the profiler's fixed capture index verifies the occ fix
    k_cvt<<<(PM * PK / 4 + 255) / 256, 256>>>(x, 0, PM * PK / 4);
    k_cvt<<<(PNO * PK / 4 + 255) / 256, 256>>>(W_qk, 1, PNO * PK / 4);
    k_tab<<<512, 256>>>(scale_p);                              // tables + FULL zeroing
    k_conv<<<dim3(PW / 4, 2, PB), 512>>>(x, dwc_w, dwc_b, out);// writes out (+bias)
    k_gemm_mma<<<dim3(PNO / 128, PM / 128), 256, GSM_TOT>>>(b_qk);
    k_post<<<PM, 256>>>();
    k_ksum<<<PB * 32, 512>>>();
    k_kv<<<PB * PNH * 16, 256>>>(x);
    k_att<<<PB * PNH * 32, 256>>>(out);                        // accumulates
}

// round 17
// speedup vs baseline: 1.0607x; 1.0318x over previous
#include <cuda_runtime.h>
#include <cuda_bf16.h>
#include <math.h>
#include <stdint.h>

// Problem constants: B=8, 64x64 image -> N=4096, C=512, head_dim=32 -> 16 heads
#define PB   8
#define PH   64
#define PW   64
#define PN   4096
#define PC   512
#define PHD  32
#define PNH  16
#define PM   (PB*PN)       // 32768 GEMM rows
#define PK   512           // GEMM K
#define PNO  1024          // GEMM out cols (2C)

// -------- scratch (device globals; no runtime allocations allowed) --------
__device__ float g_qk[(size_t)PM * PNO];            // 128 MiB qk, processed in place
__device__ float g_ksum[PB * PC];
__device__ float g_kv[PB * PNH * PHD * PHD];        // 131072 elements
__device__ __nv_bfloat16 g_xh[(size_t)PM * PK];
__device__ __nv_bfloat16 g_xl[(size_t)PM * PK];
__device__ __nv_bfloat16 g_wh[(size_t)PNO * PK];
__device__ __nv_bfloat16 g_wl[(size_t)PNO * PK];
__device__ float2 g_rope[64 * 256];                 // cos/sin table: pos x pair
__device__ float g_rs[PC];                          // 1/softplus(scale_p)

// ================= helpers (baseline PTX only) =================
__device__ __forceinline__ uint32_t smem_u32(const void* p) {
    uint32_t a;
    asm("{ .reg .u64 t; cvta.to.shared.u64 t, %1; cvt.u32.u64 %0, t; }" : "=r"(a) : "l"(p));
    return a;
}
__device__ __forceinline__ void cp16(uint32_t sdst, const void* gsrc) {
    asm volatile("cp.async.cg.shared.global [%0], [%1], 16;"
                 :: "r"(sdst), "l"((unsigned long long)__cvta_generic_to_global(gsrc)) : "memory");
}
__device__ __forceinline__ void cp_commit() { asm volatile("cp.async.commit_group;" ::: "memory"); }
__device__ __forceinline__ void cp_wait1()  { asm volatile("cp.async.wait_group 1;" ::: "memory"); }

__device__ __forceinline__ void ldsm4(uint32_t r[4], uint32_t a) {
    asm volatile("ldmatrix.sync.aligned.m8n8.x4.shared.b16 {%0,%1,%2,%3}, [%4];"
                 : "=r"(r[0]), "=r"(r[1]), "=r"(r[2]), "=r"(r[3]) : "r"(a));
}
__device__ __forceinline__ void mma16816(float c[4], const uint32_t a[4], const uint32_t b[2]) {
    asm volatile("mma.sync.aligned.m16n8k16.row.col.f32.bf16.bf16.f32 "
                 "{%0,%1,%2,%3}, {%4,%5,%6,%7}, {%8,%9}, {%0,%1,%2,%3};"
                 : "+f"(c[0]), "+f"(c[1]), "+f"(c[2]), "+f"(c[3])
                 : "r"(a[0]), "r"(a[1]), "r"(a[2]), "r"(a[3]), "r"(b[0]), "r"(b[1]));
}
__device__ __forceinline__ uint32_t swz(uint32_t base, int row, int seg) {
    return base + (uint32_t)row * 64u + (uint32_t)(((seg ^ ((row >> 1) & 3)) & 3) << 4);
}

// ================= K0: f32 -> bf16 hi/lo split =================
__global__ __launch_bounds__(256) void k_cvt(const float* __restrict__ src, int which, int n4) {
    int i = blockIdx.x * 256 + threadIdx.x;
    if (i >= n4) return;
    __nv_bfloat16* hi = which ? g_wh : g_xh;
    __nv_bfloat16* lo = which ? g_wl : g_xl;
    float4 v = ((const float4*)src)[i];
    __nv_bfloat16 h0 = __float2bfloat16_rn(v.x), h1 = __float2bfloat16_rn(v.y);
    __nv_bfloat16 h2 = __float2bfloat16_rn(v.z), h3 = __float2bfloat16_rn(v.w);
    __nv_bfloat16 l0 = __float2bfloat16_rn(v.x - __bfloat162float(h0));
    __nv_bfloat16 l1 = __float2bfloat16_rn(v.y - __bfloat162float(h1));
    __nv_bfloat16 l2 = __float2bfloat16_rn(v.z - __bfloat162float(h2));
    __nv_bfloat16 l3 = __float2bfloat16_rn(v.w - __bfloat162float(h3));
    __nv_bfloat162 hp0 = __halves2bfloat162(h0, h1), hp1 = __halves2bfloat162(h2, h3);
    __nv_bfloat162 lp0 = __halves2bfloat162(l0, l1), lp1 = __halves2bfloat162(l2, l3);
    uint2 hu, lu;
    hu.x = *(uint32_t*)&hp0; hu.y = *(uint32_t*)&hp1;
    lu.x = *(uint32_t*)&lp0; lu.y = *(uint32_t*)&lp1;
    ((uint2*)hi)[i] = hu;
    ((uint2*)lo)[i] = lu;
}

// ====== K0b: RoPE sincos + softplus-recip tables; zero ALL accumulators ======
__global__ __launch_bounds__(256) void k_tab(const float* __restrict__ scale_p) {
    int i = blockIdx.x * 256 + threadIdx.x;
    if (i < 16384) {
        int pos = i >> 8, p = i & 255;
        const float LOG1E4 = 9.2103403719761836f;
        float theta = expf(-(float)(p & 127) * (LOG1E4 / 128.f));
        float sn, cs;
        sincosf((float)pos * theta, &sn, &cs);
        g_rope[i] = make_float2(cs, sn);
        if (i < PC) g_rs[i] = 1.f / logf(1.f + expf(scale_p[i]));
        if (i < PB * PC) g_ksum[i] = 0.f;
    }
    if (i < PB * PNH * PHD * PHD) g_kv[i] = 0.f;
}

// ======== K6: depthwise 5x5 conv — 4-wide, 2-way height split, smem weights ========
__global__ __launch_bounds__(512, 2) void k_conv(const float* __restrict__ x,
                                                 const float* __restrict__ wt,
                                                 const float* __restrict__ bias,
                                                 float* __restrict__ out) {
    __shared__ float swt[25 * PHD + PHD];
    const int b = blockIdx.z;
    const int hbeg = blockIdx.y * 32;
    const int wbase = blockIdx.x * 4;
    const int c = threadIdx.x;
    const int d = c & (PHD - 1);

    for (int t = c; t < 25 * PHD; t += 512) swt[t] = wt[t];
    if (c < PHD) swt[25 * PHD + c] = bias[c];
    __syncthreads();
    const float bv = swt[25 * PHD + d];
    const float* wp = &swt[d * 25];

    float r[5][8];
    auto ld = [&](float dst[8], int rowidx) {
        if (rowidx < 0 || rowidx >= PH) {
#pragma unroll
            for (int dw = 0; dw < 8; dw++) dst[dw] = 0.f;
            return;
        }
#pragma unroll
        for (int dw = 0; dw < 8; dw++) {
            int w2 = wbase - 2 + dw;
            dst[dw] = (w2 >= 0 && w2 < PW)
                ? x[((size_t)b * PN + rowidx * PW + w2) * PC + c] : 0.f;
        }
    };
    ld(r[0], hbeg - 2); ld(r[1], hbeg - 1); ld(r[2], hbeg);
    ld(r[3], hbeg + 1); ld(r[4], hbeg + 2);

    for (int ho = hbeg; ho < hbeg + 32; ho++) {
        float s[4] = {bv, bv, bv, bv};
#pragma unroll
        for (int kh = 0; kh < 5; kh++) {
            float w0 = wp[kh * 5 + 0], w1 = wp[kh * 5 + 1], w2 = wp[kh * 5 + 2];
            float w3 = wp[kh * 5 + 3], w4 = wp[kh * 5 + 4];
#pragma unroll
            for (int ow = 0; ow < 4; ow++) {
                s[ow] = fmaf(r[kh][ow + 0], w0, s[ow]);
                s[ow] = fmaf(r[kh][ow + 1], w1, s[ow]);
                s[ow] = fmaf(r[kh][ow + 2], w2, s[ow]);
                s[ow] = fmaf(r[kh][ow + 3], w3, s[ow]);
                s[ow] = fmaf(r[kh][ow + 4], w4, s[ow]);
            }
        }
#pragma unroll
        for (int ow = 0; ow < 4; ow++)
            out[((size_t)b * PN + ho * PW + wbase + ow) * PC + c] = s[ow];
#pragma unroll
        for (int j = 0; j < 4; j++)
#pragma unroll
            for (int dw = 0; dw < 8; dw++) r[j][dw] = r[j + 1][dw];
        ld(r[4], ho + 3);
    }
}

// ================= K1: bf16-split GEMM via mma.sync (known-good) ==========
#define NSTAGE 3
#define STG_BYTES 32768
#define GSM_TOT (NSTAGE * STG_BYTES)
#define NCHUNK 16

__device__ __forceinline__ void load_stage(uint32_t sbase, int kc, int bm, int bn, int tid) {
#pragma unroll
    for (int j = 0; j < 2; j++) {
        int idx = j * 256 + tid;
        int row = idx >> 2, seg = idx & 3;
        size_t go = (size_t)kc * 32 + seg * 8;
        cp16(swz(sbase +     0, row, seg), g_xh + ((size_t)(bm + row) << 9) + go);
        cp16(swz(sbase +  8192, row, seg), g_xl + ((size_t)(bm + row) << 9) + go);
        cp16(swz(sbase + 16384, row, seg), g_wh + ((size_t)(bn + row) << 9) + go);
        cp16(swz(sbase + 24576, row, seg), g_wl + ((size_t)(bn + row) << 9) + go);
    }
}

__global__ __launch_bounds__(256) void k_gemm_mma(const float* __restrict__ bias) {
    extern __shared__ __align__(128) char smraw[];
    uint32_t sb = smem_u32(smraw);
    const int tid = threadIdx.x;
    const int wid = tid >> 5, lane = tid & 31;
    const int gid = lane >> 2, tig = lane & 3;
    const int q = lane >> 3, lr = lane & 7;
    const int bn = blockIdx.x * 128;
    const int bm = blockIdx.y * 128;
    const int wm = (wid & 1) * 64;
    const int wn = (wid >> 1) * 32;

    float acc[4][4][4];
#pragma unroll
    for (int a = 0; a < 4; a++)
#pragma unroll
        for (int b = 0; b < 4; b++)
#pragma unroll
            for (int cpos = 0; cpos < 4; cpos++) acc[a][b][cpos] = 0.f;

    load_stage(sb + 0 * STG_BYTES, 0, bm, bn, tid); cp_commit();
    load_stage(sb + 1 * STG_BYTES, 1, bm, bn, tid); cp_commit();

    for (int kc = 0; kc < NCHUNK; kc++) {
        cp_wait1();
        __syncthreads();
        if (kc + 2 < NCHUNK)
            load_stage(sb + (uint32_t)((kc + 2) % NSTAGE) * STG_BYTES, kc + 2, bm, bn, tid);
        cp_commit();

        uint32_t st = sb + (uint32_t)(kc % NSTAGE) * STG_BYTES;
        uint32_t Ah = st, Al = st + 8192, Bh = st + 16384, Bl = st + 24576;
#pragma unroll
        for (int ks = 0; ks < 2; ks++) {
            uint32_t ah[4][4], al[4][4], bh[4][2], bl[4][2];
            int arow = wm + lr + (q & 1) * 8;
            int aseg = 2 * ks + (q >> 1);
#pragma unroll
            for (int mt = 0; mt < 4; mt++) {
                ldsm4(ah[mt], swz(Ah, arow + mt * 16, aseg));
                ldsm4(al[mt], swz(Al, arow + mt * 16, aseg));
            }
            int brow = wn + lr + (q >> 1) * 8;
            int bseg = 2 * ks + (q & 1);
#pragma unroll
            for (int p = 0; p < 2; p++) {
                uint32_t t4[4];
                ldsm4(t4, swz(Bh, brow + p * 16, bseg));
                bh[2 * p][0] = t4[0]; bh[2 * p][1] = t4[1];
                bh[2 * p + 1][0] = t4[2]; bh[2 * p + 1][1] = t4[3];
                ldsm4(t4, swz(Bl, brow + p * 16, bseg));
                bl[2 * p][0] = t4[0]; bl[2 * p][1] = t4[1];
                bl[2 * p + 1][0] = t4[2]; bl[2 * p + 1][1] = t4[3];
            }
#pragma unroll
            for (int mt = 0; mt < 4; mt++)
#pragma unroll
                for (int nt = 0; nt < 4; nt++) {
                    mma16816(acc[mt][nt], ah[mt], bh[nt]);
                    mma16816(acc[mt][nt], ah[mt], bl[nt]);
                    mma16816(acc[mt][nt], al[mt], bh[nt]);
                }
        }
    }

#pragma unroll
    for (int mt = 0; mt < 4; mt++) {
        int r0 = bm + wm + mt * 16 + gid;
#pragma unroll
        for (int nt = 0; nt < 4; nt++) {
            int cb = bn + wn + nt * 8 + 2 * tig;
            float b0 = bias[cb], b1 = bias[cb + 1];
            float2 v0 = make_float2(acc[mt][nt][0] + b0, acc[mt][nt][1] + b1);
            float2 v1 = make_float2(acc[mt][nt][2] + b0, acc[mt][nt][3] + b1);
            *(float2*)&g_qk[(size_t)r0 * PNO + cb] = v0;
            *(float2*)&g_qk[(size_t)(r0 + 8) * PNO + cb] = v1;
        }
    }
}

// ================= K2: per-token transform — table-driven =================
__global__ __launch_bounds__(256) void k_post() {
    const int token = blockIdx.x;
    const int n = token & (PN - 1);
    const int hi = n >> 6;
    const int wi = n & 63;
    const int p = threadIdx.x;
    float* row = g_qk + (size_t)token * PNO;

    const int pos = (p < 128) ? hi : wi;
    float2 cssn = g_rope[pos * 256 + p];
    float cs = cssn.x, sn = cssn.y;

    float2 qv = *(float2*)&row[2 * p];
    float2 kvv = *(float2*)&row[PC + 2 * p];
    float2 rs = *(float2*)&g_rs[2 * p];

    float q0 = qv.x * cs - qv.y * sn, q1 = qv.y * cs + qv.x * sn;
    float k0 = kvv.x * cs - kvv.y * sn, k1 = kvv.y * cs + kvv.x * sn;

    q0 = q0 > 0.f ? q0 + 1.f : __expf(q0);
    q1 = q1 > 0.f ? q1 + 1.f : __expf(q1);
    k0 = k0 > 0.f ? k0 + 1.f : __expf(k0);
    k1 = k1 > 0.f ? k1 + 1.f : __expf(k1);

    q0 *= rs.x; q1 *= rs.y; k0 *= rs.x; k1 *= rs.y;

    float q0c = q0 * q0 * q0, q1c = q1 * q1 * q1;
    float k0c = k0 * k0 * k0, k1c = k1 * k1 * k1;
    float v0 = q0 * q0 + q1 * q1;
    float v1 = q0c * q0c + q1c * q1c;
    float v2 = k0 * k0 + k1 * k1;
    float v3 = k0c * k0c + k1c * k1c;

    __shared__ float warpsum[8][4];
    float v[4] = {v0, v1, v2, v3};
    const int lane = p & 31, wd = p >> 5;
#pragma unroll
    for (int t = 0; t < 4; t++) {
        float s = v[t];
#pragma unroll
        for (int off = 16; off > 0; off >>= 1) s += __shfl_down_sync(0xffffffffu, s, off);
        if (lane == 0) warpsum[wd][t] = s;
    }
    __syncthreads();
    __shared__ float fac[2];
    if (p == 0) {
        float s[4] = {0.f, 0.f, 0.f, 0.f};
        for (int w = 0; w < 8; w++)
            for (int t = 0; t < 4; t++) s[t] += warpsum[w][t];
        fac[0] = sqrtf(s[0] / s[1]);
        fac[1] = sqrtf(s[2] / s[3]);
    }
    __syncthreads();
    float fq = fac[0], fk = fac[1];
    *(float2*)&row[2 * p]      = make_float2(q0c * fq, q1c * fq);
    *(float2*)&row[PC + 2 * p] = make_float2(k0c * fk, k1c * fk);
}

// ====== K4: kv = k^T v + fused k-sums — 16-way n-split, outer-product tiles ======
// 256 threads: 4 n-subsets x 64 (4d x 4e) register tiles; 16 FMA per 2 LDS.128.
__global__ __launch_bounds__(256) void k_kv(const float* __restrict__ x) {
    const int b = blockIdx.x >> 8;           // 2048 blocks
    const int h = (blockIdx.x >> 4) & 15;
    const int sl = blockIdx.x & 15;          // 256-row slice
    const int tid = threadIdx.x;

    __shared__ __align__(16) float sk[32][36];
    __shared__ __align__(16) float sv[32][36];
    __shared__ float sred[3][64][17];        // subsets 1..3 partial staging
    __shared__ float skred[8][32];           // ksum partials

    const int lr = tid >> 5, lc = tid & 31;
    const int s = tid >> 6, u = tid & 63;    // subset / tile id
    const int dg = u >> 3, eg = u & 7;       // d-group, e-group

    float acc[4][4];
#pragma unroll
    for (int i = 0; i < 4; i++)
#pragma unroll
        for (int j = 0; j < 4; j++) acc[i][j] = 0.f;
    float ksacc = 0.f;

    const int n0beg = sl * 256;
    for (int t = 0; t < 8; t++) {
        int n0 = n0beg + t * 32;
        __syncthreads();
#pragma unroll
        for (int rr = lr; rr < 32; rr += 8) {
            size_t rbase = ((size_t)b * PN + n0 + rr);
            float kvl = g_qk[rbase * PNO + PC + h * PHD + lc];
            sk[rr][lc] = kvl;
            ksacc += kvl;
            sv[rr][lc] = x[rbase * PC + h * PHD + lc];
        }
        __syncthreads();
#pragma unroll
        for (int nn = s * 8; nn < s * 8 + 8; nn++) {
            float4 k4 = *(const float4*)&sk[nn][dg * 4];
            float4 v4 = *(const float4*)&sv[nn][eg * 4];
            float kk[4] = {k4.x, k4.y, k4.z, k4.w};
            float vv[4] = {v4.x, v4.y, v4.z, v4.w};
#pragma unroll
            for (int i = 0; i < 4; i++)
#pragma unroll
                for (int j = 0; j < 4; j++)
                    acc[i][j] = fmaf(kk[i], vv[j], acc[i][j]);
        }
    }
    __syncthreads();
    skred[lr][lc] = ksacc;
    if (s > 0) {
#pragma unroll
        for (int i = 0; i < 4; i++)
#pragma unroll
            for (int j = 0; j < 4; j++)
                sred[s - 1][u][i * 4 + j] = acc[i][j];
    }
    __syncthreads();
    if (tid < 32) {
        float sum = 0.f;
#pragma unroll
        for (int r = 0; r < 8; r++) sum += skred[r][tid];
        atomicAdd(&g_ksum[b * PC + h * PHD + tid], sum);
    }
    if (s == 0) {
        const float s2 = 1.f / (float)PN;
#pragma unroll
        for (int i = 0; i < 4; i++)
#pragma unroll
            for (int j = 0; j < 4; j++) {
                float v = acc[i][j] + sred[0][u][i * 4 + j]
                        + sred[1][u][i * 4 + j] + sred[2][u][i * 4 + j];
                atomicAdd(&g_kv[(((size_t)b * PNH + h) * PHD + dg * 4 + i) * PHD + eg * 4 + j],
                          v * s2);
            }
    }
}

// ================= K5: out += (q@kv)*z =================
__global__ __launch_bounds__(256) void k_att(float* __restrict__ out) {
    const int bid = blockIdx.x;
    const int b = bid >> 9;
    const int h = (bid >> 5) & 15;
    const int tile = bid & 31;
    const int tid = threadIdx.x;
    const int lane = tid & 31;
    const int w = tid >> 5;

    __shared__ float skv[32][33];
    __shared__ float skm[32];
    __shared__ float sq[8][32];

    for (int i = tid; i < 1024; i += 256)
        skv[i >> 5][i & 31] = g_kv[((size_t)b * PNH + h) * 1024 + i];
    if (tid < 32)
        skm[tid] = g_ksum[b * PC + h * PHD + tid] * (1.f / (float)PN);
    __syncthreads();

    for (int chunk = 0; chunk < 16; chunk++) {
        int t = tile * 128 + chunk * 8 + w;
        float qv = g_qk[((size_t)b * PN + t) * PNO + h * PHD + lane];
        __syncwarp();
        sq[w][lane] = qv;
        __syncwarp();
        float zdot = 0.f, acc = 0.f;
#pragma unroll
        for (int d = 0; d < 32; d++) {
            float qd = sq[w][d];
            zdot = fmaf(qd, skm[d], zdot);
            acc  = fmaf(qd, skv[d][lane], acc);
        }
        float z = 1.f / (zdot + 1e-6f);
        out[((size_t)b * PN + t) * PC + h * PHD + lane] += acc * z;
    }
}

// ================= launch =================
extern "C" void kernel_launch(void* const* d_in, const int* in_sizes, int n_in,
                              void* d_out, int out_size) {
    (void)in_sizes; (void)n_in; (void)out_size;
    const float* x       = (const float*)d_in[0];
    const float* W_qk    = (const float*)d_in[1];
    const float* b_qk    = (const float*)d_in[2];
    const float* scale_p = (const float*)d_in[3];
    const float* dwc_w   = (const float*)d_in[4];
    const float* dwc_b   = (const float*)d_in[5];
    float* out = (float*)d_out;

    cudaFuncSetAttribute(k_gemm_mma, cudaFuncAttributeMaxDynamicSharedMemorySize, GSM_TOT);

    k_cvt<<<(PM * PK / 4 + 255) / 256, 256>>>(x, 0, PM * PK / 4);
    k_cvt<<<(PNO * PK / 4 + 255) / 256, 256>>>(W_qk, 1, PNO * PK / 4);
    k_tab<<<512, 256>>>(scale_p);                              // tables + FULL zeroing
    k_conv<<<dim3(PW / 4, 2, PB), 512>>>(x, dwc_w, dwc_b, out);// writes out (+bias)
    k_gemm_mma<<<dim3(PNO / 128, PM / 128), 256, GSM_TOT>>>(b_qk);
    k_post<<<PM, 256>>>();
    k_kv<<<PB * PNH * 16, 256>>>(x);                           // kv + fused ksum
    k_att<<<PB * PNH * 32, 256>>>(out);                        // accumulates
}